// round 3
// baseline (speedup 1.0000x reference)
#include <cuda_runtime.h>
#include <math.h>

#define BB   64
#define TT   256
#define HH   1024
#define PP   128
#define LL   256
#define GG   4096     // 4*HH
#define MTOT 16384    // BB*TT

// ---- scratch (device globals: allocation-free contract) ----
__device__ float g_xg[(size_t)MTOT * GG];    // 268 MB: per-layer input-transform (reused layer0->layer1)
__device__ float g_hseq[(size_t)MTOT * HH];  // 64 MB: hidden sequence (h1, later overwritten by h2)
__device__ float g_hbuf[2][BB * HH];         // double-buffered recurrent h
__device__ float g_h0[BB * HH];              // fc_init output (shared init for both layers)
__device__ float g_c[BB * HH];               // cell state

__device__ __forceinline__ float sigf(float x) { return 1.0f / (1.0f + __expf(-x)); }

// ---------------- h0 = z @ fc_init_w^T + b ; also seed h/c state ----------------
__global__ void k_init(const float* __restrict__ z,
                       const float* __restrict__ w,
                       const float* __restrict__ bias)
{
    __shared__ float zs[LL];
    int b = blockIdx.y;
    int h = blockIdx.x * 256 + threadIdx.x;
    for (int i = threadIdx.x; i < LL; i += 256) zs[i] = z[b * LL + i];
    __syncthreads();
    const float* wr = w + (size_t)h * LL;
    float acc = bias[h];
    #pragma unroll 8
    for (int k = 0; k < LL; k++) acc += zs[k] * wr[k];
    g_h0[b * HH + h]      = acc;
    g_hbuf[0][b * HH + h] = acc;
    g_c[b * HH + h]       = 0.0f;
}

// ---------------- reset state before layer 1 ----------------
__global__ void k_reset()
{
    int i = blockIdx.x * 256 + threadIdx.x;
    g_hbuf[0][i] = g_h0[i];
    g_c[i] = 0.0f;
}

// ---------------- generic tiled GEMM:  C[m,n] = act(bias(n) + sum_k A[m,k]*W[n,k]) ----------------
// BM=128, BN=64, BK=16, 256 threads, 8x4 micro-tile, register-prefetch pipeline.
// MODE: 0 = A from Aptr (row-major, lda), 1 = gather x_in from (start_token, target), 2 = A = g_hseq
// CDST: 0 = write Cptr, 1 = write g_xg
// ACT : 0 = identity, 1 = sigmoid
template<int MODE, int CDST, int ACT>
__global__ __launch_bounds__(256, 2)
void k_gemm(const float* __restrict__ Aptr, int K, int lda,
            const float* __restrict__ W,
            const float* __restrict__ bias1, const float* __restrict__ bias2,
            const float* __restrict__ tgt, const float* __restrict__ start,
            float* __restrict__ Cptr, int ldc)
{
    __shared__ __align__(16) float As[16][132];
    __shared__ __align__(16) float Ws[16][68];

    const float* Ab = (MODE == 2) ? (const float*)g_hseq : Aptr;
    float* C = (CDST == 1) ? (float*)g_xg : Cptr;

    int m0 = blockIdx.x * 128;
    int n0 = blockIdx.y * 64;
    int tid = threadIdx.x;
    int row0 = (tid >> 4) * 8;
    int col0 = (tid & 15) * 4;

    // loaders: A tile 128x16 (two float4 per thread), W tile 64x16 (one float4)
    int lk  = (tid & 3) * 4;
    int ar0 = tid >> 2;            // rows 0..63
    int ar1 = (tid + 256) >> 2;    // rows 64..127
    int wrow = tid >> 2;           // 0..63
    const float* wsrc = &W[(size_t)(n0 + wrow) * K + lk];

    auto loadA = [&](int k0, int arow) -> float4 {
        int m = m0 + arow;
        if (MODE == 1) {
            int t = m & (TT - 1);
            if (t == 0) return *(const float4*)&start[k0 + lk];
            return *(const float4*)&tgt[(size_t)(m - 1) * PP + k0 + lk];
        }
        return *(const float4*)&Ab[(size_t)m * lda + k0 + lk];
    };

    float acc[8][4];
    #pragma unroll
    for (int i = 0; i < 8; i++)
        #pragma unroll
        for (int j = 0; j < 4; j++) acc[i][j] = 0.0f;

    int nt = K >> 4;
    float4 av0 = loadA(0, ar0);
    float4 av1 = loadA(0, ar1);
    float4 wv  = *(const float4*)&wsrc[0];

    As[lk+0][ar0]=av0.x; As[lk+1][ar0]=av0.y; As[lk+2][ar0]=av0.z; As[lk+3][ar0]=av0.w;
    As[lk+0][ar1]=av1.x; As[lk+1][ar1]=av1.y; As[lk+2][ar1]=av1.z; As[lk+3][ar1]=av1.w;
    Ws[lk+0][wrow]=wv.x; Ws[lk+1][wrow]=wv.y; Ws[lk+2][wrow]=wv.z; Ws[lk+3][wrow]=wv.w;
    __syncthreads();

    for (int tile = 0; tile < nt; tile++) {
        if (tile + 1 < nt) {
            int k0 = (tile + 1) << 4;
            av0 = loadA(k0, ar0);
            av1 = loadA(k0, ar1);
            wv  = *(const float4*)&wsrc[k0];
        }
        #pragma unroll
        for (int kk = 0; kk < 16; kk++) {
            float4 a0 = *(const float4*)&As[kk][row0];
            float4 a1 = *(const float4*)&As[kk][row0 + 4];
            float4 wq = *(const float4*)&Ws[kk][col0];
            float ar[8] = {a0.x, a0.y, a0.z, a0.w, a1.x, a1.y, a1.z, a1.w};
            float wr4[4] = {wq.x, wq.y, wq.z, wq.w};
            #pragma unroll
            for (int i = 0; i < 8; i++)
                #pragma unroll
                for (int j = 0; j < 4; j++)
                    acc[i][j] += ar[i] * wr4[j];
        }
        if (tile + 1 < nt) {
            __syncthreads();
            As[lk+0][ar0]=av0.x; As[lk+1][ar0]=av0.y; As[lk+2][ar0]=av0.z; As[lk+3][ar0]=av0.w;
            As[lk+0][ar1]=av1.x; As[lk+1][ar1]=av1.y; As[lk+2][ar1]=av1.z; As[lk+3][ar1]=av1.w;
            Ws[lk+0][wrow]=wv.x; Ws[lk+1][wrow]=wv.y; Ws[lk+2][wrow]=wv.z; Ws[lk+3][wrow]=wv.w;
            __syncthreads();
        }
    }

    // epilogue
    float bv[4];
    #pragma unroll
    for (int j = 0; j < 4; j++) {
        int n = n0 + col0 + j;
        float bb = bias1[n];
        if (bias2) bb += bias2[n];
        bv[j] = bb;
    }
    #pragma unroll
    for (int i = 0; i < 8; i++) {
        size_t m = (size_t)(m0 + row0 + i);
        float4 o;
        float v0 = acc[i][0] + bv[0];
        float v1 = acc[i][1] + bv[1];
        float v2 = acc[i][2] + bv[2];
        float v3 = acc[i][3] + bv[3];
        if (ACT) { v0 = sigf(v0); v1 = sigf(v1); v2 = sigf(v2); v3 = sigf(v3); }
        o.x = v0; o.y = v1; o.z = v2; o.w = v3;
        *(float4*)&C[m * ldc + n0 + col0] = o;
    }
}

// ---------------- one recurrence step (fused GEMM + LSTM cell) ----------------
// grid = 128 CTAs; CTA owns h-dims [j0, j0+8), computes all 4 gates for all 64 batches.
// Output tile 64(batch) x 32(col = gate*8 + jj), K = 1024. Reads h from g_hbuf[pin],
// writes new h to g_hbuf[pin^1] (double-buffer: avoids cross-CTA read/write race).
__global__ __launch_bounds__(256, 1)
void k_step(const float* __restrict__ Whh, int t, int pin)
{
    __shared__ __align__(16) float Hs[16][68];   // [k][batch]
    __shared__ __align__(16) float Wss[16][36];  // [k][col]
    __shared__ float Gs[64][33];                 // gate values [batch][col]

    const float* hin = g_hbuf[pin];
    float* hout = g_hbuf[pin ^ 1];

    int j0 = blockIdx.x * 8;
    int tid = threadIdx.x;
    int col = tid & 31;            // gate*8 + jj
    int row0 = (tid >> 5) * 8;     // batch base per warp

    // loader indices: H tile 64x16 (1 float4/thread), W tile 32x16 (tid<128)
    int lrow = tid >> 2;           // 0..63 (H), 0..31 (W, when tid<128)
    int lk = (tid & 3) * 4;
    int wn = ((lrow >> 3) * HH) + j0 + (lrow & 7);   // Whh row for this loader thread

    float acc[8] = {0,0,0,0,0,0,0,0};

    float4 hv = *(const float4*)&hin[lrow * HH + lk];
    float4 wv = make_float4(0.f, 0.f, 0.f, 0.f);
    if (tid < 128) wv = *(const float4*)&Whh[(size_t)wn * HH + lk];

    Hs[lk+0][lrow]=hv.x; Hs[lk+1][lrow]=hv.y; Hs[lk+2][lrow]=hv.z; Hs[lk+3][lrow]=hv.w;
    if (tid < 128) { Wss[lk+0][lrow]=wv.x; Wss[lk+1][lrow]=wv.y; Wss[lk+2][lrow]=wv.z; Wss[lk+3][lrow]=wv.w; }
    __syncthreads();

    for (int tile = 0; tile < 64; tile++) {
        if (tile < 63) {
            int k0 = (tile + 1) << 4;
            hv = *(const float4*)&hin[lrow * HH + k0 + lk];
            if (tid < 128) wv = *(const float4*)&Whh[(size_t)wn * HH + k0 + lk];
        }
        #pragma unroll
        for (int kk = 0; kk < 16; kk++) {
            float w = Wss[kk][col];
            float4 a0 = *(const float4*)&Hs[kk][row0];
            float4 a1 = *(const float4*)&Hs[kk][row0 + 4];
            acc[0] += a0.x * w; acc[1] += a0.y * w; acc[2] += a0.z * w; acc[3] += a0.w * w;
            acc[4] += a1.x * w; acc[5] += a1.y * w; acc[6] += a1.z * w; acc[7] += a1.w * w;
        }
        if (tile < 63) {
            __syncthreads();
            Hs[lk+0][lrow]=hv.x; Hs[lk+1][lrow]=hv.y; Hs[lk+2][lrow]=hv.z; Hs[lk+3][lrow]=hv.w;
            if (tid < 128) { Wss[lk+0][lrow]=wv.x; Wss[lk+1][lrow]=wv.y; Wss[lk+2][lrow]=wv.z; Wss[lk+3][lrow]=wv.w; }
            __syncthreads();
        }
    }

    // add precomputed input-transform xg and stage gates in SMEM
    {
        int gate = col >> 3, jj = col & 7;
        size_t xoff = (size_t)gate * HH + j0 + jj;
        #pragma unroll
        for (int i = 0; i < 8; i++) {
            int b = row0 + i;
            Gs[b][col] = acc[i] + g_xg[((size_t)(b * TT + t)) * GG + xoff];
        }
    }
    __syncthreads();

    // LSTM cell update for this CTA's 8 h-dims x 64 batches
    for (int p = tid; p < 512; p += 256) {
        int b = p >> 3;
        int jj = p & 7;
        int j = j0 + jj;
        float gi = Gs[b][jj];
        float gf = Gs[b][8 + jj];
        float gg = Gs[b][16 + jj];
        float go = Gs[b][24 + jj];
        float c = sigf(gf) * g_c[b * HH + j] + sigf(gi) * tanhf(gg);
        float h = sigf(go) * tanhf(c);
        g_c[b * HH + j] = c;
        hout[b * HH + j] = h;
        g_hseq[((size_t)b * TT + t) * HH + j] = h;
    }
}

// ---------------- launch ----------------
extern "C" void kernel_launch(void* const* d_in, const int* in_sizes, int n_in,
                              void* d_out, int out_size)
{
    (void)in_sizes; (void)n_in; (void)out_size;
    const float* z     = (const float*)d_in[0];
    const float* tgt   = (const float*)d_in[1];
    const float* fw    = (const float*)d_in[2];
    const float* fb    = (const float*)d_in[3];
    const float* start = (const float*)d_in[4];
    const float* Wih0  = (const float*)d_in[5];
    const float* Whh0  = (const float*)d_in[6];
    const float* bih0  = (const float*)d_in[7];
    const float* bhh0  = (const float*)d_in[8];
    const float* Wih1  = (const float*)d_in[9];
    const float* Whh1  = (const float*)d_in[10];
    const float* bih1  = (const float*)d_in[11];
    const float* bhh1  = (const float*)d_in[12];
    const float* outw  = (const float*)d_in[13];
    const float* outb  = (const float*)d_in[14];
    float* out = (float*)d_out;

    // h0 = fc_init(z); seed h/c
    k_init<<<dim3(HH / 256, BB), 256>>>(z, fw, fb);

    // layer 0: xg0 = x_in @ Wih0^T + bih0 + bhh0   (x_in gathered from start_token/target)
    k_gemm<1, 1, 0><<<dim3(MTOT / 128, GG / 64), 256>>>(
        nullptr, PP, PP, Wih0, bih0, bhh0, tgt, start, nullptr, GG);

    for (int t = 0; t < TT; t++)
        k_step<<<HH / 8, 256>>>(Whh0, t, t & 1);

    // layer 1: reset state, xg1 = h1seq @ Wih1^T + bih1 + bhh1
    k_reset<<<(BB * HH) / 256, 256>>>();
    k_gemm<2, 1, 0><<<dim3(MTOT / 128, GG / 64), 256>>>(
        nullptr, HH, HH, Wih1, bih1, bhh1, nullptr, nullptr, nullptr, GG);

    for (int t = 0; t < TT; t++)
        k_step<<<HH / 8, 256>>>(Whh1, t, t & 1);

    // out = sigmoid(h2seq @ out_w^T + out_b)
    k_gemm<2, 0, 1><<<dim3(MTOT / 128, PP / 64), 256>>>(
        nullptr, HH, HH, outw, outb, nullptr, nullptr, nullptr, out, PP);
}

// round 5
// speedup vs baseline: 1.0010x; 1.0010x over previous
#include <cuda_runtime.h>
#include <math.h>

#define BB   64
#define TT   256
#define HH   1024
#define PP   128
#define LL   256
#define GG   4096     // 4*HH
#define MTOT 16384    // BB*TT

// ---- scratch (device globals: allocation-free contract) ----
__device__ float g_xg[(size_t)MTOT * GG];    // 268 MB: per-layer input-transform (reused layer0->layer1)
__device__ float g_hseq[(size_t)MTOT * HH];  // 64 MB: hidden sequence (h1, later overwritten by h2)
__device__ float g_hbuf[2][BB * HH];         // double-buffered recurrent h
__device__ float g_h0[BB * HH];              // fc_init output (shared init for both layers)
__device__ float g_c[BB * HH];               // cell state

__device__ __forceinline__ float sigf(float x) { return 1.0f / (1.0f + __expf(-x)); }

// ---------------- h0 = z @ fc_init_w^T + b ; also seed h/c state ----------------
__global__ void k_init(const float* __restrict__ z,
                       const float* __restrict__ w,
                       const float* __restrict__ bias)
{
    __shared__ float zs[LL];
    int b = blockIdx.y;
    int h = blockIdx.x * 256 + threadIdx.x;
    for (int i = threadIdx.x; i < LL; i += 256) zs[i] = z[b * LL + i];
    __syncthreads();
    const float* wr = w + (size_t)h * LL;
    float acc = bias[h];
    #pragma unroll 8
    for (int k = 0; k < LL; k++) acc += zs[k] * wr[k];
    g_h0[b * HH + h]      = acc;
    g_hbuf[0][b * HH + h] = acc;
    g_c[b * HH + h]       = 0.0f;
}

// ---------------- reset state before layer 1 ----------------
__global__ void k_reset()
{
    int i = blockIdx.x * 256 + threadIdx.x;
    g_hbuf[0][i] = g_h0[i];
    g_c[i] = 0.0f;
}

// ---------------- generic tiled GEMM:  C[m,n] = act(bias(n) + sum_k A[m,k]*W[n,k]) ----------------
// BM=128, BN=64, BK=16, 256 threads, 8x4 micro-tile, register-prefetch pipeline.
// MODE: 0 = A from Aptr (row-major, lda), 1 = gather x_in from (start_token, target), 2 = A = g_hseq
// CDST: 0 = write Cptr, 1 = write g_xg
// ACT : 0 = identity, 1 = sigmoid
template<int MODE, int CDST, int ACT>
__global__ __launch_bounds__(256, 2)
void k_gemm(const float* __restrict__ Aptr, int K, int lda,
            const float* __restrict__ W,
            const float* __restrict__ bias1, const float* __restrict__ bias2,
            const float* __restrict__ tgt, const float* __restrict__ start,
            float* __restrict__ Cptr, int ldc)
{
    __shared__ __align__(16) float As[16][132];
    __shared__ __align__(16) float Ws[16][68];

    const float* Ab = (MODE == 2) ? (const float*)g_hseq : Aptr;
    float* C = (CDST == 1) ? (float*)g_xg : Cptr;

    int m0 = blockIdx.x * 128;
    int n0 = blockIdx.y * 64;
    int tid = threadIdx.x;
    int row0 = (tid >> 4) * 8;
    int col0 = (tid & 15) * 4;

    // loaders: A tile 128x16 (two float4 per thread), W tile 64x16 (one float4)
    int lk  = (tid & 3) * 4;
    int ar0 = tid >> 2;            // rows 0..63
    int ar1 = (tid + 256) >> 2;    // rows 64..127
    int wrow = tid >> 2;           // 0..63
    const float* wsrc = &W[(size_t)(n0 + wrow) * K + lk];

    auto loadA = [&](int k0, int arow) -> float4 {
        int m = m0 + arow;
        if (MODE == 1) {
            int t = m & (TT - 1);
            if (t == 0) return *(const float4*)&start[k0 + lk];
            return *(const float4*)&tgt[(size_t)(m - 1) * PP + k0 + lk];
        }
        return *(const float4*)&Ab[(size_t)m * lda + k0 + lk];
    };

    float acc[8][4];
    #pragma unroll
    for (int i = 0; i < 8; i++)
        #pragma unroll
        for (int j = 0; j < 4; j++) acc[i][j] = 0.0f;

    int nt = K >> 4;
    float4 av0 = loadA(0, ar0);
    float4 av1 = loadA(0, ar1);
    float4 wv  = *(const float4*)&wsrc[0];

    As[lk+0][ar0]=av0.x; As[lk+1][ar0]=av0.y; As[lk+2][ar0]=av0.z; As[lk+3][ar0]=av0.w;
    As[lk+0][ar1]=av1.x; As[lk+1][ar1]=av1.y; As[lk+2][ar1]=av1.z; As[lk+3][ar1]=av1.w;
    Ws[lk+0][wrow]=wv.x; Ws[lk+1][wrow]=wv.y; Ws[lk+2][wrow]=wv.z; Ws[lk+3][wrow]=wv.w;
    __syncthreads();

    for (int tile = 0; tile < nt; tile++) {
        if (tile + 1 < nt) {
            int k0 = (tile + 1) << 4;
            av0 = loadA(k0, ar0);
            av1 = loadA(k0, ar1);
            wv  = *(const float4*)&wsrc[k0];
        }
        #pragma unroll
        for (int kk = 0; kk < 16; kk++) {
            float4 a0 = *(const float4*)&As[kk][row0];
            float4 a1 = *(const float4*)&As[kk][row0 + 4];
            float4 wq = *(const float4*)&Ws[kk][col0];
            float ar[8] = {a0.x, a0.y, a0.z, a0.w, a1.x, a1.y, a1.z, a1.w};
            float wr4[4] = {wq.x, wq.y, wq.z, wq.w};
            #pragma unroll
            for (int i = 0; i < 8; i++)
                #pragma unroll
                for (int j = 0; j < 4; j++)
                    acc[i][j] += ar[i] * wr4[j];
        }
        if (tile + 1 < nt) {
            __syncthreads();
            As[lk+0][ar0]=av0.x; As[lk+1][ar0]=av0.y; As[lk+2][ar0]=av0.z; As[lk+3][ar0]=av0.w;
            As[lk+0][ar1]=av1.x; As[lk+1][ar1]=av1.y; As[lk+2][ar1]=av1.z; As[lk+3][ar1]=av1.w;
            Ws[lk+0][wrow]=wv.x; Ws[lk+1][wrow]=wv.y; Ws[lk+2][wrow]=wv.z; Ws[lk+3][wrow]=wv.w;
            __syncthreads();
        }
    }

    // epilogue
    float bv[4];
    #pragma unroll
    for (int j = 0; j < 4; j++) {
        int n = n0 + col0 + j;
        float bb = bias1[n];
        if (bias2) bb += bias2[n];
        bv[j] = bb;
    }
    #pragma unroll
    for (int i = 0; i < 8; i++) {
        size_t m = (size_t)(m0 + row0 + i);
        float4 o;
        float v0 = acc[i][0] + bv[0];
        float v1 = acc[i][1] + bv[1];
        float v2 = acc[i][2] + bv[2];
        float v3 = acc[i][3] + bv[3];
        if (ACT) { v0 = sigf(v0); v1 = sigf(v1); v2 = sigf(v2); v3 = sigf(v3); }
        o.x = v0; o.y = v1; o.z = v2; o.w = v3;
        *(float4*)&C[m * ldc + n0 + col0] = o;
    }
}

// ---------------- one recurrence step (fused GEMM + LSTM cell) ----------------
// grid = 128 CTAs; CTA owns h-dims [j0, j0+8), computes all 4 gates for all 64 batches.
// Output tile 64(batch) x 32(col = gate*8 + jj), K = 1024. Reads h from g_hbuf[pin],
// writes new h to g_hbuf[pin^1] (double-buffer: avoids cross-CTA read/write race).
__global__ __launch_bounds__(256, 1)
void k_step(const float* __restrict__ Whh, int t, int pin)
{
    __shared__ __align__(16) float Hs[16][68];   // [k][batch]
    __shared__ __align__(16) float Wss[16][36];  // [k][col]
    __shared__ float Gs[64][33];                 // gate values [batch][col]

    const float* hin = g_hbuf[pin];
    float* hout = g_hbuf[pin ^ 1];

    int j0 = blockIdx.x * 8;
    int tid = threadIdx.x;
    int col = tid & 31;            // gate*8 + jj
    int row0 = (tid >> 5) * 8;     // batch base per warp

    // loader indices: H tile 64x16 (1 float4/thread), W tile 32x16 (tid<128)
    int lrow = tid >> 2;           // 0..63 (H), 0..31 (W, when tid<128)
    int lk = (tid & 3) * 4;
    int wn = ((lrow >> 3) * HH) + j0 + (lrow & 7);   // Whh row for this loader thread

    float acc[8] = {0,0,0,0,0,0,0,0};

    float4 hv = *(const float4*)&hin[lrow * HH + lk];
    float4 wv = make_float4(0.f, 0.f, 0.f, 0.f);
    if (tid < 128) wv = *(const float4*)&Whh[(size_t)wn * HH + lk];

    Hs[lk+0][lrow]=hv.x; Hs[lk+1][lrow]=hv.y; Hs[lk+2][lrow]=hv.z; Hs[lk+3][lrow]=hv.w;
    if (tid < 128) { Wss[lk+0][lrow]=wv.x; Wss[lk+1][lrow]=wv.y; Wss[lk+2][lrow]=wv.z; Wss[lk+3][lrow]=wv.w; }
    __syncthreads();

    for (int tile = 0; tile < 64; tile++) {
        if (tile < 63) {
            int k0 = (tile + 1) << 4;
            hv = *(const float4*)&hin[lrow * HH + k0 + lk];
            if (tid < 128) wv = *(const float4*)&Whh[(size_t)wn * HH + k0 + lk];
        }
        #pragma unroll
        for (int kk = 0; kk < 16; kk++) {
            float w = Wss[kk][col];
            float4 a0 = *(const float4*)&Hs[kk][row0];
            float4 a1 = *(const float4*)&Hs[kk][row0 + 4];
            acc[0] += a0.x * w; acc[1] += a0.y * w; acc[2] += a0.z * w; acc[3] += a0.w * w;
            acc[4] += a1.x * w; acc[5] += a1.y * w; acc[6] += a1.z * w; acc[7] += a1.w * w;
        }
        if (tile < 63) {
            __syncthreads();
            Hs[lk+0][lrow]=hv.x; Hs[lk+1][lrow]=hv.y; Hs[lk+2][lrow]=hv.z; Hs[lk+3][lrow]=hv.w;
            if (tid < 128) { Wss[lk+0][lrow]=wv.x; Wss[lk+1][lrow]=wv.y; Wss[lk+2][lrow]=wv.z; Wss[lk+3][lrow]=wv.w; }
            __syncthreads();
        }
    }

    // add precomputed input-transform xg and stage gates in SMEM
    {
        int gate = col >> 3, jj = col & 7;
        size_t xoff = (size_t)gate * HH + j0 + jj;
        #pragma unroll
        for (int i = 0; i < 8; i++) {
            int b = row0 + i;
            Gs[b][col] = acc[i] + g_xg[((size_t)(b * TT + t)) * GG + xoff];
        }
    }
    __syncthreads();

    // LSTM cell update for this CTA's 8 h-dims x 64 batches
    for (int p = tid; p < 512; p += 256) {
        int b = p >> 3;
        int jj = p & 7;
        int j = j0 + jj;
        float gi = Gs[b][jj];
        float gf = Gs[b][8 + jj];
        float gg = Gs[b][16 + jj];
        float go = Gs[b][24 + jj];
        float c = sigf(gf) * g_c[b * HH + j] + sigf(gi) * tanhf(gg);
        float h = sigf(go) * tanhf(c);
        g_c[b * HH + j] = c;
        hout[b * HH + j] = h;
        g_hseq[((size_t)b * TT + t) * HH + j] = h;
    }
}

// ---------------- launch ----------------
extern "C" void kernel_launch(void* const* d_in, const int* in_sizes, int n_in,
                              void* d_out, int out_size)
{
    (void)in_sizes; (void)n_in; (void)out_size;
    const float* z     = (const float*)d_in[0];
    const float* tgt   = (const float*)d_in[1];
    const float* fw    = (const float*)d_in[2];
    const float* fb    = (const float*)d_in[3];
    const float* start = (const float*)d_in[4];
    const float* Wih0  = (const float*)d_in[5];
    const float* Whh0  = (const float*)d_in[6];
    const float* bih0  = (const float*)d_in[7];
    const float* bhh0  = (const float*)d_in[8];
    const float* Wih1  = (const float*)d_in[9];
    const float* Whh1  = (const float*)d_in[10];
    const float* bih1  = (const float*)d_in[11];
    const float* bhh1  = (const float*)d_in[12];
    const float* outw  = (const float*)d_in[13];
    const float* outb  = (const float*)d_in[14];
    float* out = (float*)d_out;

    // h0 = fc_init(z); seed h/c
    k_init<<<dim3(HH / 256, BB), 256>>>(z, fw, fb);

    // layer 0: xg0 = x_in @ Wih0^T + bih0 + bhh0   (x_in gathered from start_token/target)
    k_gemm<1, 1, 0><<<dim3(MTOT / 128, GG / 64), 256>>>(
        nullptr, PP, PP, Wih0, bih0, bhh0, tgt, start, nullptr, GG);

    for (int t = 0; t < TT; t++)
        k_step<<<HH / 8, 256>>>(Whh0, t, t & 1);

    // layer 1: reset state, xg1 = h1seq @ Wih1^T + bih1 + bhh1
    k_reset<<<(BB * HH) / 256, 256>>>();
    k_gemm<2, 1, 0><<<dim3(MTOT / 128, GG / 64), 256>>>(
        nullptr, HH, HH, Wih1, bih1, bhh1, nullptr, nullptr, nullptr, GG);

    for (int t = 0; t < TT; t++)
        k_step<<<HH / 8, 256>>>(Whh1, t, t & 1);

    // out = sigmoid(h2seq @ out_w^T + out_b)
    k_gemm<2, 0, 1><<<dim3(MTOT / 128, PP / 64), 256>>>(
        nullptr, HH, HH, outw, outb, nullptr, nullptr, nullptr, out, PP);
}

// round 8
// speedup vs baseline: 3.1417x; 3.1387x over previous
#include <cuda_runtime.h>
#include <cuda_bf16.h>
#include <math.h>

#define BB   64
#define TT   256
#define HH   1024
#define PP   128
#define LL   256
#define GG   4096
#define MTOT 16384
#define NCTA 128

// ---------------- device-global scratch (allocation-free contract) ----------------
__device__ float         g_xg [(size_t)MTOT * GG];   // input-transform (per layer, reused)
__device__ __nv_bfloat16 g_xhi[(size_t)MTOT * HH];   // hseq hi (layer output / GEMM A)
__device__ __nv_bfloat16 g_xlo[(size_t)MTOT * HH];
__device__ __nv_bfloat16 g_inhi[(size_t)MTOT * PP];  // layer-0 input
__device__ __nv_bfloat16 g_inlo[(size_t)MTOT * PP];
__device__ __nv_bfloat16 g_whi[(size_t)GG * HH];     // weight split scratch (sequential reuse)
__device__ __nv_bfloat16 g_wlo[(size_t)GG * HH];
__device__ __nv_bfloat16 g_rhi[2][BB * HH];          // recurrent h ring
__device__ __nv_bfloat16 g_rlo[2][BB * HH];
__device__ __nv_bfloat16 g_h0hi[BB * HH];
__device__ __nv_bfloat16 g_h0lo[BB * HH];
__device__ unsigned g_barc;                          // barrier counter (self-resetting)
__device__ unsigned g_barg;                          // barrier generation (monotonic)

__device__ __forceinline__ float sigf(float x) { return 1.0f / (1.0f + __expf(-x)); }

__device__ __forceinline__ void split_bf16(float v, __nv_bfloat16& hi, __nv_bfloat16& lo) {
    hi = __float2bfloat16(v);
    lo = __float2bfloat16(v - __bfloat162float(hi));
}

__device__ __forceinline__ void cp16(void* smem, const void* gmem) {
    unsigned s = (unsigned)__cvta_generic_to_shared(smem);
    asm volatile("cp.async.cg.shared.global [%0], [%1], 16;\n" :: "r"(s), "l"(gmem));
}
#define CP_COMMIT() asm volatile("cp.async.commit_group;\n" ::: "memory")
#define CP_WAIT1()  asm volatile("cp.async.wait_group 1;\n" ::: "memory")
#define CP_WAIT0()  asm volatile("cp.async.wait_group 0;\n" ::: "memory")

__device__ __forceinline__ void mma16816(float* c,
    unsigned a0, unsigned a1, unsigned a2, unsigned a3, unsigned b0, unsigned b1)
{
    asm volatile(
        "mma.sync.aligned.m16n8k16.row.col.f32.bf16.bf16.f32 "
        "{%0,%1,%2,%3},{%4,%5,%6,%7},{%8,%9},{%0,%1,%2,%3};\n"
        : "+f"(c[0]), "+f"(c[1]), "+f"(c[2]), "+f"(c[3])
        : "r"(a0), "r"(a1), "r"(a2), "r"(a3), "r"(b0), "r"(b1));
}

__device__ __forceinline__ void st_cg_b16(__nv_bfloat16* p, __nv_bfloat16 v) {
    unsigned short u = *(unsigned short*)&v;
    asm volatile("st.global.cg.u16 [%0], %1;\n" :: "l"(p), "h"(u));
}

// ---------------- h0 = z @ fc_init_w^T + b ; seed ring[0] ----------------
__global__ void k_init(const float* __restrict__ z, const float* __restrict__ w,
                       const float* __restrict__ bias)
{
    __shared__ float zs[LL];
    int b = blockIdx.y;
    int h = blockIdx.x * 256 + threadIdx.x;
    for (int i = threadIdx.x; i < LL; i += 256) zs[i] = z[b * LL + i];
    __syncthreads();
    const float* wr = w + (size_t)h * LL;
    float acc = bias[h];
    #pragma unroll 8
    for (int k = 0; k < LL; k++) acc += zs[k] * wr[k];
    __nv_bfloat16 hi, lo; split_bf16(acc, hi, lo);
    int idx = b * HH + h;
    g_h0hi[idx] = hi;  g_h0lo[idx] = lo;
    g_rhi[0][idx] = hi; g_rlo[0][idx] = lo;
}

__global__ void k_seed()
{
    int i = blockIdx.x * 256 + threadIdx.x;
    g_rhi[0][i] = g_h0hi[i];
    g_rlo[0][i] = g_h0lo[i];
}

// ---------------- layer-0 input (start token / shifted target) -> bf16 pair ----------------
__global__ void k_convin(const float* __restrict__ tgt, const float* __restrict__ start)
{
    int idx = blockIdx.x * 256 + threadIdx.x;      // over MTOT*PP
    int m = idx >> 7, p = idx & (PP - 1);
    int t = m & (TT - 1);
    float v = (t == 0) ? start[p] : tgt[(size_t)(m - 1) * PP + p];
    __nv_bfloat16 hi, lo; split_bf16(v, hi, lo);
    g_inhi[idx] = hi; g_inlo[idx] = lo;
}

// ---------------- weight matrix -> bf16 pair scratch ----------------
__global__ void k_convw(const float* __restrict__ src, int n)
{
    int i = blockIdx.x * 256 + threadIdx.x;
    if (i < n) {
        __nv_bfloat16 hi, lo; split_bf16(src[i], hi, lo);
        g_whi[i] = hi; g_wlo[i] = lo;
    }
}

// ---------------- split-bf16 GEMM: C[M,N] = act(bias + A[M,K] * B[N,K]^T) ----------------
// BM=64 BN=64 BK=32, 256 threads, 3-pass split, cp.async double buffer.
template<int ACT>
__global__ __launch_bounds__(256, 2)
void k_bgemm(const __nv_bfloat16* __restrict__ Ahi, const __nv_bfloat16* __restrict__ Alo,
             const __nv_bfloat16* __restrict__ Bhi, const __nv_bfloat16* __restrict__ Blo,
             int K,
             const float* __restrict__ bias1, const float* __restrict__ bias2,
             float* __restrict__ C, int ldc)
{
    __shared__ __align__(16) __nv_bfloat16 sA[2][2][64 * 40];  // [buf][hi/lo][row*40+k]
    __shared__ __align__(16) __nv_bfloat16 sB[2][2][64 * 40];

    int m0 = blockIdx.x * 64, n0 = blockIdx.y * 64;
    int tid = threadIdx.x;
    int lane = tid & 31, w = tid >> 5;
    int g = lane >> 2, tg = lane & 3;
    int m0w = (w & 3) * 16, n0w = (w >> 2) * 32;

    int srow = tid >> 2, sseg = (tid & 3) * 8;
    const __nv_bfloat16* gAh = Ahi + (size_t)(m0 + srow) * K + sseg;
    const __nv_bfloat16* gAl = Alo + (size_t)(m0 + srow) * K + sseg;
    const __nv_bfloat16* gBh = Bhi + (size_t)(n0 + srow) * K + sseg;
    const __nv_bfloat16* gBl = Blo + (size_t)(n0 + srow) * K + sseg;
    int soff = srow * 40 + sseg;

    float acc[4][4];
    #pragma unroll
    for (int i = 0; i < 4; i++)
        #pragma unroll
        for (int j = 0; j < 4; j++) acc[i][j] = 0.0f;

    int nch = K >> 5;
    cp16(&sA[0][0][soff], gAh); cp16(&sA[0][1][soff], gAl);
    cp16(&sB[0][0][soff], gBh); cp16(&sB[0][1][soff], gBl);
    CP_COMMIT();

    for (int c = 0; c < nch; c++) {
        int buf = c & 1;
        if (c + 1 < nch) {
            int ko = (c + 1) * 32;
            cp16(&sA[buf ^ 1][0][soff], gAh + ko); cp16(&sA[buf ^ 1][1][soff], gAl + ko);
            cp16(&sB[buf ^ 1][0][soff], gBh + ko); cp16(&sB[buf ^ 1][1][soff], gBl + ko);
            CP_COMMIT();
            CP_WAIT1();
        } else {
            CP_WAIT0();
        }
        __syncthreads();

        const __nv_bfloat16* Ah = &sA[buf][0][0];
        const __nv_bfloat16* Al = &sA[buf][1][0];
        const __nv_bfloat16* Bh = &sB[buf][0][0];
        const __nv_bfloat16* Bl = &sB[buf][1][0];
        #pragma unroll
        for (int kk = 0; kk < 2; kk++) {
            int kb = kk * 16 + tg * 2;
            unsigned ah0 = *(const unsigned*)&Ah[(m0w + g) * 40 + kb];
            unsigned ah1 = *(const unsigned*)&Ah[(m0w + g + 8) * 40 + kb];
            unsigned ah2 = *(const unsigned*)&Ah[(m0w + g) * 40 + kb + 8];
            unsigned ah3 = *(const unsigned*)&Ah[(m0w + g + 8) * 40 + kb + 8];
            unsigned al0 = *(const unsigned*)&Al[(m0w + g) * 40 + kb];
            unsigned al1 = *(const unsigned*)&Al[(m0w + g + 8) * 40 + kb];
            unsigned al2 = *(const unsigned*)&Al[(m0w + g) * 40 + kb + 8];
            unsigned al3 = *(const unsigned*)&Al[(m0w + g + 8) * 40 + kb + 8];
            #pragma unroll
            for (int nt = 0; nt < 4; nt++) {
                int nn = (n0w + nt * 8 + g) * 40 + kb;
                unsigned bh0 = *(const unsigned*)&Bh[nn];
                unsigned bh1 = *(const unsigned*)&Bh[nn + 8];
                unsigned bl0 = *(const unsigned*)&Bl[nn];
                unsigned bl1 = *(const unsigned*)&Bl[nn + 8];
                mma16816(acc[nt], ah0, ah1, ah2, ah3, bh0, bh1);
                mma16816(acc[nt], al0, al1, al2, al3, bh0, bh1);
                mma16816(acc[nt], ah0, ah1, ah2, ah3, bl0, bl1);
            }
        }
        __syncthreads();
    }

    #pragma unroll
    for (int nt = 0; nt < 4; nt++) {
        int col = n0 + n0w + nt * 8 + tg * 2;
        float b0v = bias1[col]     + (bias2 ? bias2[col]     : 0.0f);
        float b1v = bias1[col + 1] + (bias2 ? bias2[col + 1] : 0.0f);
        float v0 = acc[nt][0] + b0v, v1 = acc[nt][1] + b1v;
        float v2 = acc[nt][2] + b0v, v3 = acc[nt][3] + b1v;
        if (ACT) { v0 = sigf(v0); v1 = sigf(v1); v2 = sigf(v2); v3 = sigf(v3); }
        int r0 = m0 + m0w + g, r1 = r0 + 8;
        *(float2*)&C[(size_t)r0 * ldc + col] = make_float2(v0, v1);
        *(float2*)&C[(size_t)r1 * ldc + col] = make_float2(v2, v3);
    }
}

// ---------------- persistent recurrence: all 256 steps of one layer ----------------
// 128 CTAs (1/SM due to 212KB smem; 128 <= 148 SMs -> all co-resident in wave 1).
// CTA owns h-dims [j0,j0+8) -> 32 gate cols. Whh slice bf16 hi/lo resident in SMEM
// for the whole kernel; h state circulates through a double-buffered global ring
// (st.global.cg writer / cp.async.cg reader, both L2-scope, fenced at the barrier).
#define WPITCH 1032
#define HPITCH 136
#define SMEM_PERSIST (2*32*WPITCH*2 + 4*64*HPITCH*2 + 64*33*4 + 512*4)

__global__ __launch_bounds__(256, 1)
void k_persist(const float* __restrict__ Whh, const float* __restrict__ xg,
               __nv_bfloat16* __restrict__ rhi, __nv_bfloat16* __restrict__ rlo,
               __nv_bfloat16* __restrict__ shi, __nv_bfloat16* __restrict__ slo)
{
    extern __shared__ char sm_raw[];
    __nv_bfloat16* Wh = (__nv_bfloat16*)sm_raw;           // [32][WPITCH]
    __nv_bfloat16* Wl = Wh + 32 * WPITCH;
    __nv_bfloat16* Hs = Wl + 32 * WPITCH;                 // [buf2][hi/lo][64*HPITCH]
    float* Gs = (float*)(Hs + 4 * 64 * HPITCH);           // [64][33]
    float* Cs = Gs + 64 * 33;                             // [512] cell state

    int tid = threadIdx.x;
    int lane = tid & 31, w = tid >> 5;
    int g = lane >> 2, tg = lane & 3;
    int m0w = (w >> 1) * 16, n0w = (w & 1) * 16;
    int j0 = blockIdx.x * 8;

    // one-time: split W slice into SMEM; zero cell state
    for (int s = tid; s < 32 * 256; s += 256) {
        int n = s >> 8;                 // col 0..31 = gate*8+jj
        int ks = (s & 255) * 4;
        int grow = (n >> 3) * HH + j0 + (n & 7);
        float4 v = *(const float4*)&Whh[(size_t)grow * HH + ks];
        float vv[4] = {v.x, v.y, v.z, v.w};
        #pragma unroll
        for (int q = 0; q < 4; q++) {
            __nv_bfloat16 hi, lo; split_bf16(vv[q], hi, lo);
            Wh[n * WPITCH + ks + q] = hi;
            Wl[n * WPITCH + ks + q] = lo;
        }
    }
    for (int s = tid; s < 512; s += 256) Cs[s] = 0.0f;
    __syncthreads();

    for (int t = 0; t < TT; t++) {
        const __nv_bfloat16* hh = rhi + (size_t)(t & 1) * BB * HH;
        const __nv_bfloat16* hl = rlo + (size_t)(t & 1) * BB * HH;
        __nv_bfloat16* ohh = rhi + (size_t)((t & 1) ^ 1) * BB * HH;
        __nv_bfloat16* ohl = rlo + (size_t)((t & 1) ^ 1) * BB * HH;

        // xg prefetch (overlaps MMA)
        float xv[2][4];
        #pragma unroll
        for (int e = 0; e < 2; e++) {
            int p = tid + e * 256;
            int b = p >> 3, jj = p & 7;
            size_t base = ((size_t)(b * TT + t)) * GG + j0 + jj;
            #pragma unroll
            for (int q = 0; q < 4; q++) xv[e][q] = __ldg(&xg[base + (size_t)q * HH]);
        }

        float acc[2][4];
        #pragma unroll
        for (int i = 0; i < 2; i++)
            #pragma unroll
            for (int j = 0; j < 4; j++) acc[i][j] = 0.0f;

        // stage chunk 0
        #pragma unroll
        for (int i = 0; i < 4; i++) {
            int slot = i * 256 + tid;
            int row = slot >> 4, seg = (slot & 15) * 8;
            cp16(&Hs[0 * 64 * HPITCH + row * HPITCH + seg], hh + row * HH + seg);
            cp16(&Hs[1 * 64 * HPITCH + row * HPITCH + seg], hl + row * HH + seg);
        }
        CP_COMMIT();

        for (int c = 0; c < 8; c++) {
            int buf = c & 1;
            if (c < 7) {
                int k0 = (c + 1) * 128;
                #pragma unroll
                for (int i = 0; i < 4; i++) {
                    int slot = i * 256 + tid;
                    int row = slot >> 4, seg = (slot & 15) * 8;
                    cp16(&Hs[((buf ^ 1) * 2 + 0) * 64 * HPITCH + row * HPITCH + seg], hh + row * HH + k0 + seg);
                    cp16(&Hs[((buf ^ 1) * 2 + 1) * 64 * HPITCH + row * HPITCH + seg], hl + row * HH + k0 + seg);
                }
                CP_COMMIT();
                CP_WAIT1();
            } else {
                CP_WAIT0();
            }
            __syncthreads();

            const __nv_bfloat16* Ah = &Hs[(buf * 2 + 0) * 64 * HPITCH];
            const __nv_bfloat16* Al = &Hs[(buf * 2 + 1) * 64 * HPITCH];
            #pragma unroll
            for (int kk = 0; kk < 8; kk++) {
                int kb = kk * 16 + tg * 2;
                unsigned ah0 = *(const unsigned*)&Ah[(m0w + g) * HPITCH + kb];
                unsigned ah1 = *(const unsigned*)&Ah[(m0w + g + 8) * HPITCH + kb];
                unsigned ah2 = *(const unsigned*)&Ah[(m0w + g) * HPITCH + kb + 8];
                unsigned ah3 = *(const unsigned*)&Ah[(m0w + g + 8) * HPITCH + kb + 8];
                unsigned al0 = *(const unsigned*)&Al[(m0w + g) * HPITCH + kb];
                unsigned al1 = *(const unsigned*)&Al[(m0w + g + 8) * HPITCH + kb];
                unsigned al2 = *(const unsigned*)&Al[(m0w + g) * HPITCH + kb + 8];
                unsigned al3 = *(const unsigned*)&Al[(m0w + g + 8) * HPITCH + kb + 8];
                int kw = c * 128 + kb;
                #pragma unroll
                for (int nt = 0; nt < 2; nt++) {
                    int nn = (n0w + nt * 8 + g) * WPITCH + kw;
                    unsigned bh0 = *(const unsigned*)&Wh[nn];
                    unsigned bh1 = *(const unsigned*)&Wh[nn + 8];
                    unsigned bl0 = *(const unsigned*)&Wl[nn];
                    unsigned bl1 = *(const unsigned*)&Wl[nn + 8];
                    mma16816(acc[nt], ah0, ah1, ah2, ah3, bh0, bh1);
                    mma16816(acc[nt], al0, al1, al2, al3, bh0, bh1);
                    mma16816(acc[nt], ah0, ah1, ah2, ah3, bl0, bl1);
                }
            }
            __syncthreads();
        }

        // stage Whh*h into Gs  (row=batch, col=gate*8+jj)
        #pragma unroll
        for (int nt = 0; nt < 2; nt++) {
            int col = n0w + nt * 8 + tg * 2;
            Gs[(m0w + g) * 33 + col]     = acc[nt][0];
            Gs[(m0w + g) * 33 + col + 1] = acc[nt][1];
            Gs[(m0w + g + 8) * 33 + col]     = acc[nt][2];
            Gs[(m0w + g + 8) * 33 + col + 1] = acc[nt][3];
        }
        __syncthreads();

        // LSTM cell: 8 h-dims x 64 batches
        #pragma unroll
        for (int e = 0; e < 2; e++) {
            int p = tid + e * 256;
            int b = p >> 3, jj = p & 7;
            float gi = Gs[b * 33 + jj]      + xv[e][0];
            float gf = Gs[b * 33 + 8 + jj]  + xv[e][1];
            float gg = Gs[b * 33 + 16 + jj] + xv[e][2];
            float go = Gs[b * 33 + 24 + jj] + xv[e][3];
            float cc = sigf(gf) * Cs[p] + sigf(gi) * tanhf(gg);
            float h  = sigf(go) * tanhf(cc);
            Cs[p] = cc;
            __nv_bfloat16 hhi, hlo; split_bf16(h, hhi, hlo);
            size_t oidx = (size_t)b * HH + j0 + jj;
            st_cg_b16(ohh + oidx, hhi);
            st_cg_b16(ohl + oidx, hlo);
            size_t sidx = ((size_t)(b * TT + t)) * HH + j0 + jj;
            shi[sidx] = hhi;
            slo[sidx] = hlo;
        }

        // grid barrier (all 128 CTAs resident; generation counter, self-resetting count)
        __syncthreads();
        __threadfence();
        if (tid == 0) {
            unsigned my = *((volatile unsigned*)&g_barg);
            if (atomicAdd(&g_barc, 1u) == NCTA - 1) {
                g_barc = 0;
                __threadfence();
                atomicExch(&g_barg, my + 1);
            } else {
                while (*((volatile unsigned*)&g_barg) == my) __nanosleep(32);
            }
            __threadfence();
        }
        __syncthreads();
    }
}

// ---------------- launch ----------------
extern "C" void kernel_launch(void* const* d_in, const int* in_sizes, int n_in,
                              void* d_out, int out_size)
{
    (void)in_sizes; (void)n_in; (void)out_size;
    const float* z     = (const float*)d_in[0];
    const float* tgt   = (const float*)d_in[1];
    const float* fw    = (const float*)d_in[2];
    const float* fb    = (const float*)d_in[3];
    const float* start = (const float*)d_in[4];
    const float* Wih0  = (const float*)d_in[5];
    const float* Whh0  = (const float*)d_in[6];
    const float* bih0  = (const float*)d_in[7];
    const float* bhh0  = (const float*)d_in[8];
    const float* Wih1  = (const float*)d_in[9];
    const float* Whh1  = (const float*)d_in[10];
    const float* bih1  = (const float*)d_in[11];
    const float* bhh1  = (const float*)d_in[12];
    const float* outw  = (const float*)d_in[13];
    const float* outb  = (const float*)d_in[14];
    float* out = (float*)d_out;

    float* xg_p;
    __nv_bfloat16 *xhi_p, *xlo_p, *inhi_p, *inlo_p, *whi_p, *wlo_p, *rhi_p, *rlo_p;
    cudaGetSymbolAddress((void**)&xg_p,   g_xg);
    cudaGetSymbolAddress((void**)&xhi_p,  g_xhi);
    cudaGetSymbolAddress((void**)&xlo_p,  g_xlo);
    cudaGetSymbolAddress((void**)&inhi_p, g_inhi);
    cudaGetSymbolAddress((void**)&inlo_p, g_inlo);
    cudaGetSymbolAddress((void**)&whi_p,  g_whi);
    cudaGetSymbolAddress((void**)&wlo_p,  g_wlo);
    cudaGetSymbolAddress((void**)&rhi_p,  g_rhi);
    cudaGetSymbolAddress((void**)&rlo_p,  g_rlo);

    cudaFuncSetAttribute(k_persist, cudaFuncAttributeMaxDynamicSharedMemorySize, SMEM_PERSIST);

    // h0 + seed ring; layer-0 input -> bf16 pair
    k_init<<<dim3(HH / 256, BB), 256>>>(z, fw, fb);
    k_convin<<<(MTOT * PP) / 256, 256>>>(tgt, start);

    // layer 0: xg0 = x_in @ Wih0^T + b  -> recurrence
    k_convw<<<(GG * PP + 255) / 256, 256>>>(Wih0, GG * PP);
    k_bgemm<0><<<dim3(MTOT / 64, GG / 64), 256>>>(inhi_p, inlo_p, whi_p, wlo_p, PP,
                                                  bih0, bhh0, xg_p, GG);
    k_persist<<<NCTA, 256, SMEM_PERSIST>>>(Whh0, xg_p, rhi_p, rlo_p, xhi_p, xlo_p);

    // layer 1: xg1 = h1seq @ Wih1^T + b (consumes g_xhi before layer-1 overwrites it)
    k_convw<<<(GG * HH + 255) / 256, 256>>>(Wih1, GG * HH);
    k_bgemm<0><<<dim3(MTOT / 64, GG / 64), 256>>>(xhi_p, xlo_p, whi_p, wlo_p, HH,
                                                  bih1, bhh1, xg_p, GG);
    k_seed<<<(BB * HH) / 256, 256>>>();
    k_persist<<<NCTA, 256, SMEM_PERSIST>>>(Whh1, xg_p, rhi_p, rlo_p, xhi_p, xlo_p);

    // out = sigmoid(h2seq @ out_w^T + out_b)
    k_convw<<<(PP * HH + 255) / 256, 256>>>(outw, PP * HH);
    k_bgemm<1><<<dim3(MTOT / 64, PP / 64), 256>>>(xhi_p, xlo_p, whi_p, wlo_p, HH,
                                                  outb, nullptr, out, PP);
}